// round 7
// baseline (speedup 1.0000x reference)
#include <cuda_runtime.h>
#include <cuda_fp16.h>
#include <cstdint>
#include <math.h>

#define B_SZ     16384
#define T_SZ     10
#define H_SZ     256
#define G_SZ     1024
#define N_LABELS 500
#define ROWS     (B_SZ * T_SZ)     // 163840
#define XPAD     64

typedef unsigned long long u64;
typedef unsigned int u32;
typedef __half fp16;

// ---------------- device scratch (no allocations allowed) --------------------
__device__ fp16  g_x  [(size_t)ROWS * XPAD];     // gathered input, fp16 [b*T+t][64]
__device__ fp16  g_h1 [(size_t)ROWS * H_SZ];     // layer0 outputs [b*T+t][256]
__device__ fp16  g_ha [(size_t)B_SZ * H_SZ];     // h ping-pong
__device__ fp16  g_hb [(size_t)B_SZ * H_SZ];
__device__ float g_c  [(size_t)B_SZ * H_SZ];
__device__ float g_bias0[G_SZ];                  // gate-permuted combined biases
__device__ float g_bias1[G_SZ];
// combined weight chunk images (hi/lo fp16, pre-swizzled): [tile*nkcTot+kc][256][64]
__device__ fp16 g_w0_hi[4 * 5 * 16384], g_w0_lo[4 * 5 * 16384];   // [Whh0|Wih0]
__device__ fp16 g_w1_hi[4 * 8 * 16384], g_w1_lo[4 * 8 * 16384];   // [Whh1|Wih1]
__device__ fp16 g_wo_hi[2 * 4 * 16384], g_wo_lo[2 * 4 * 16384];   // Wout

// ---------------- PTX helpers ------------------------------------------------
__device__ __forceinline__ u32 smem_u32(const void* p) {
    u32 a; asm("{ .reg .u64 t; cvta.to.shared.u64 t, %1; cvt.u32.u64 %0, t; }"
               : "=r"(a) : "l"(p));
    return a;
}
__device__ __forceinline__ void cp16(u32 dst, const void* src) {
    asm volatile("cp.async.cg.shared.global [%0], [%1], 16;" :: "r"(dst), "l"(src));
}
__device__ __forceinline__ void cp_commit() { asm volatile("cp.async.commit_group;"); }
template <int N> __device__ __forceinline__ void cp_wait() {
    asm volatile("cp.async.wait_group %0;" :: "n"(N));
}
__device__ __forceinline__ void ldm4(u32& r0, u32& r1, u32& r2, u32& r3, u32 addr) {
    asm volatile("ldmatrix.sync.aligned.m8n8.x4.shared.b16 {%0,%1,%2,%3}, [%4];"
                 : "=r"(r0), "=r"(r1), "=r"(r2), "=r"(r3) : "r"(addr));
}
__device__ __forceinline__ void mma16(float* d, const u32* a, const u32* b) {
    asm volatile("mma.sync.aligned.m16n8k16.row.col.f32.f16.f16.f32 "
                 "{%0,%1,%2,%3}, {%4,%5,%6,%7}, {%8,%9}, {%0,%1,%2,%3};"
                 : "+f"(d[0]), "+f"(d[1]), "+f"(d[2]), "+f"(d[3])
                 : "r"(a[0]), "r"(a[1]), "r"(a[2]), "r"(a[3]), "r"(b[0]), "r"(b[1]));
}

// ---------------- prep kernels ----------------------------------------------
__global__ void prep_bias(const float* bih0, const float* bhh0,
                          const float* bih1, const float* bhh1) {
    int p = blockIdx.x * blockDim.x + threadIdx.x;
    if (p < G_SZ) {
        int j = p >> 2, g = p & 3, n = g * 256 + j;
        g_bias0[p] = bih0[n] + bhh0[n];
        g_bias1[p] = bih1[n] + bhh1[n];
    }
}

// pack W[Nrows,Kw] (optionally gate-permuted rows) into combined chunk image
// at kc offset kc0, nkcSrc chunks, image has nkcTot chunks per tile.
__global__ void prep_wimg(const float* __restrict__ W, int Kw, int Nrows, int perm,
                          fp16* __restrict__ hi, fp16* __restrict__ lo,
                          int nkcTot, int kc0, int nkcSrc, int ntiles) {
    long total = (long)ntiles * nkcSrc * 16384;
    long id = (long)blockIdx.x * blockDim.x + threadIdx.x;
    if (id >= total) return;
    int c  = (int)(id & 63);
    int r  = (int)((id >> 6) & 255);
    long tk = id >> 14;
    int kcs = (int)(tk % nkcSrc), nt = (int)(tk / nkcSrc);
    int p = nt * 256 + r;
    int n = perm ? ((p & 3) * 256 + (p >> 2)) : p;
    int k = kcs * 64 + c;
    float v = (n < Nrows && k < Kw) ? W[(size_t)n * Kw + k] : 0.f;
    fp16 h = __float2half(v);
    size_t pos = ((size_t)(nt * nkcTot + kc0 + kcs) * 256 + r) * 64
               + (size_t)((((c >> 3) ^ (r & 7)) << 3) | (c & 7));
    hi[pos] = h;
    lo[pos] = __float2half(v - __half2float(h));
}

// embedding gather -> fp16 X [ROWS, 64]
__global__ void gather_kernel(const int* __restrict__ car, const int* __restrict__ reg,
                              const int* __restrict__ poi, const int* __restrict__ week,
                              const int* __restrict__ timei,
                              const float* __restrict__ ce, const float* __restrict__ re,
                              const float* __restrict__ pe, const float* __restrict__ we,
                              const float* __restrict__ te) {
    long i = (long)blockIdx.x * blockDim.x + threadIdx.x;
    if (i >= (long)ROWS * XPAD) return;
    long r = i / XPAD; int j = (int)(i % XPAD);
    float v = 0.f;
    if      (j < 16) v = ce[(size_t)car  [r] * 16 + j];
    else if (j < 24) v = re[(size_t)reg  [r] * 8  + (j - 16)];
    else if (j < 28) v = pe[(size_t)poi  [r] * 4  + (j - 24)];
    else if (j < 31) v = we[(size_t)week [r] * 3  + (j - 28)];
    else if (j < 39) v = te[(size_t)timei[r] * 8  + (j - 31)];
    g_x[i] = __float2half(v);
}

// ---------------- GEMM config ------------------------------------------------
// BM=128, BN=128, BK=64; 256 thr, 8 warps 2x4 (warp tile 64x32);
// 2 passes per k16 (W hi + W lo).  Stage = A 16KB | Whi 16KB | Wlo 16KB.
#define STG_BYTES 49152
#define SM_BYTES  (2 * STG_BYTES)   // 98304

#define GEMM_COMPUTE_CHUNK(aBase, bBase)                                           \
    _Pragma("unroll")                                                              \
    for (int k16 = 0; k16 < 4; ++k16) {                                            \
        const int kb8 = k16 * 2 + lk;                                              \
        u32 bh[4][2], bl[4][2];                                                    \
        _Pragma("unroll")                                                          \
        for (int blk = 0; blk < 2; ++blk) {                                        \
            int row = n_w + blk * 16 + lrow;                                       \
            u32 ad = (bBase) + ((row * 64 + ((kb8 ^ (row & 7)) << 3)) << 1);       \
            u32 r0, r1, r2, r3;                                                    \
            ldm4(r0, r1, r2, r3, ad);                                              \
            bh[blk * 2][0] = r0; bh[blk * 2][1] = r2;                              \
            bh[blk * 2 + 1][0] = r1; bh[blk * 2 + 1][1] = r3;                      \
            ldm4(r0, r1, r2, r3, ad + 16384);                                      \
            bl[blk * 2][0] = r0; bl[blk * 2][1] = r2;                              \
            bl[blk * 2 + 1][0] = r1; bl[blk * 2 + 1][1] = r3;                      \
        }                                                                          \
        _Pragma("unroll")                                                          \
        for (int mt = 0; mt < 4; ++mt) {                                           \
            int row = m_w + mt * 16 + lrow;                                        \
            u32 ad = (aBase) + ((row * 64 + ((kb8 ^ (row & 7)) << 3)) << 1);       \
            u32 af[4];                                                             \
            ldm4(af[0], af[1], af[2], af[3], ad);                                  \
            _Pragma("unroll")                                                      \
            for (int nt = 0; nt < 4; ++nt) mma16(acc[mt][nt], af, bh[nt]);         \
            _Pragma("unroll")                                                      \
            for (int nt = 0; nt < 4; ++nt) mma16(acc[mt][nt], af, bl[nt]);         \
        }                                                                          \
    }

// ---------------- recurrent GEMM + fused LSTM cell ----------------------------
// gates[b, p] = [h_prev | xext] @ [Whh | Wix]^T + bias   (p = 4j+g permuted)
// A chunks: kc < kH from hprev (lda 256); kc >= kH from xsrc (lda ldx).
__global__ void __launch_bounds__(256)
gemm_rec(const fp16* __restrict__ hprev,
         const fp16* __restrict__ xsrc, int ldx, int kH, int kcBegin, int nkc,
         const fp16* __restrict__ Whi, const fp16* __restrict__ Wlo,
         const float* __restrict__ biasPerm,
         float* __restrict__ c, int czero,
         fp16* __restrict__ hout, fp16* __restrict__ h1out, int t)
{
    extern __shared__ __align__(1024) char sm[];
    const u32 sb = smem_u32(sm);
    const int tid = threadIdx.x, wid = tid >> 5, lid = tid & 31;
    const int m0 = blockIdx.y * 128;
    const int n0 = blockIdx.x * 128;
    const int tile = n0 >> 8, rowbase = n0 & 255;
    const int m_w = (wid >> 2) * 64, n_w = (wid & 2 ? 64 : 0) + (wid & 1) * 32;

    float acc[4][4][4];
#pragma unroll
    for (int a = 0; a < 4; a++)
#pragma unroll
        for (int b = 0; b < 4; b++)
#pragma unroll
            for (int e = 0; e < 4; e++) acc[a][b][e] = 0.f;

    const int au = tid & 7, ar = tid >> 3;
    auto load_stage = [&](int s, int kc) {
        u32 base = sb + s * STG_BYTES;
        const fp16* asrc;
        int alda, kin;
        if (kc < kH) { asrc = hprev; alda = H_SZ; kin = kc * 64; }
        else         { asrc = xsrc;  alda = ldx;  kin = (kc - kH) * 64; }
#pragma unroll
        for (int i = 0; i < 4; i++) {
            int r = ar + i * 32;
            u32 d = base + ((r * 64 + ((au ^ (r & 7)) << 3)) << 1);
            cp16(d, asrc + (size_t)(m0 + r) * alda + kin + au * 8);
        }
        const size_t ib = (size_t)(tile * nkc + kc) * 16384 + (size_t)rowbase * 64;
#pragma unroll
        for (int i = 0; i < 4; i++) {
            int j = tid + i * 256;
            cp16(base + 16384 + j * 16, Whi + ib + (size_t)j * 8);
            cp16(base + 32768 + j * 16, Wlo + ib + (size_t)j * 8);
        }
        cp_commit();
    };

    const int lrow = lid & 15, lk = lid >> 4;

    load_stage(0, kcBegin);
    for (int kc = kcBegin; kc < nkc; ++kc) {
        int rel = kc - kcBegin;
        if (kc + 1 < nkc) { load_stage((rel + 1) & 1, kc + 1); cp_wait<1>(); }
        else              { cp_wait<0>(); }
        __syncthreads();
        const u32 aBase = sb + (rel & 1) * STG_BYTES;
        const u32 bBase = aBase + 16384;
        GEMM_COMPUTE_CHUNK(aBase, bBase)
        __syncthreads();
    }

    // fused LSTM cell epilogue: lane pairs exchange half-quadruples
    const int odd = lid & 1;
#pragma unroll
    for (int mt = 0; mt < 4; ++mt) {
        int r0 = m0 + m_w + mt * 16 + (lid >> 2);
#pragma unroll
        for (int nt = 0; nt < 4; ++nt) {
            float* a4 = acc[mt][nt];
            int p = n0 + n_w + nt * 8 + (lid & 3) * 2;
            int j = p >> 2;
            float s0 = odd ? a4[0] : a4[2];
            float s1 = odd ? a4[1] : a4[3];
            float r0v = __shfl_xor_sync(0xFFFFFFFFu, s0, 1);
            float r1v = __shfl_xor_sync(0xFFFFFFFFu, s1, 1);
            float gi, gf, gg, go;
            int row;
            if (odd) { gi = r0v;  gf = r1v;  gg = a4[2]; go = a4[3]; row = r0 + 8; }
            else     { gi = a4[0]; gf = a4[1]; gg = r0v; go = r1v;  row = r0; }
            float4 bv = *(const float4*)(biasPerm + 4 * j);
            gi += bv.x; gf += bv.y; gg += bv.z; go += bv.w;
            gi = 1.f / (1.f + expf(-gi));
            gf = 1.f / (1.f + expf(-gf));
            go = 1.f / (1.f + expf(-go));
            gg = tanhf(gg);
            size_t ci = (size_t)row * H_SZ + j;
            float cold = czero ? 0.f : c[ci];
            float cn = gf * cold + gi * gg;
            float hn = go * tanhf(cn);
            c[ci] = cn;
            hout[ci] = __float2half(hn);
            if (h1out) h1out[((size_t)row * T_SZ + t) * H_SZ + j] = __float2half(hn);
        }
    }
}

// ---------------- plain GEMM (output head) ------------------------------------
__global__ void __launch_bounds__(256)
gemm_head(const fp16* __restrict__ A,
          const fp16* __restrict__ Whi, const fp16* __restrict__ Wlo,
          const float* __restrict__ bias,
          float* __restrict__ C, int ldc, int Nvalid)
{
    extern __shared__ __align__(1024) char sm[];
    const u32 sb = smem_u32(sm);
    const int tid = threadIdx.x, wid = tid >> 5, lid = tid & 31;
    const int m0 = blockIdx.y * 128;
    const int n0 = blockIdx.x * 128;
    const int tile = n0 >> 8, rowbase = n0 & 255;
    const int m_w = (wid >> 2) * 64, n_w = (wid & 2 ? 64 : 0) + (wid & 1) * 32;
    const int nkc = 4;

    float acc[4][4][4];
#pragma unroll
    for (int a = 0; a < 4; a++)
#pragma unroll
        for (int b = 0; b < 4; b++)
#pragma unroll
            for (int e = 0; e < 4; e++) acc[a][b][e] = 0.f;

    const int au = tid & 7, ar = tid >> 3;
    auto load_stage = [&](int s, int kc) {
        u32 base = sb + s * STG_BYTES;
#pragma unroll
        for (int i = 0; i < 4; i++) {
            int r = ar + i * 32;
            u32 d = base + ((r * 64 + ((au ^ (r & 7)) << 3)) << 1);
            cp16(d, A + (size_t)(m0 + r) * H_SZ + kc * 64 + au * 8);
        }
        const size_t ib = (size_t)(tile * nkc + kc) * 16384 + (size_t)rowbase * 64;
#pragma unroll
        for (int i = 0; i < 4; i++) {
            int j = tid + i * 256;
            cp16(base + 16384 + j * 16, Whi + ib + (size_t)j * 8);
            cp16(base + 32768 + j * 16, Wlo + ib + (size_t)j * 8);
        }
        cp_commit();
    };

    const int lrow = lid & 15, lk = lid >> 4;

    load_stage(0, 0);
    for (int kc = 0; kc < nkc; ++kc) {
        if (kc + 1 < nkc) { load_stage((kc + 1) & 1, kc + 1); cp_wait<1>(); }
        else              { cp_wait<0>(); }
        __syncthreads();
        const u32 aBase = sb + (kc & 1) * STG_BYTES;
        const u32 bBase = aBase + 16384;
        GEMM_COMPUTE_CHUNK(aBase, bBase)
        __syncthreads();
    }

#pragma unroll
    for (int mt = 0; mt < 4; ++mt) {
        int r0 = m0 + m_w + mt * 16 + (lid >> 2);
#pragma unroll
        for (int nt = 0; nt < 4; ++nt) {
            int cN = n0 + n_w + nt * 8 + (lid & 3) * 2;
            if (cN < Nvalid) {
                float bx = bias[cN], by = bias[cN + 1];
                *(float2*)(C + (size_t)r0 * ldc + cN) =
                    make_float2(acc[mt][nt][0] + bx, acc[mt][nt][1] + by);
                *(float2*)(C + (size_t)(r0 + 8) * ldc + cN) =
                    make_float2(acc[mt][nt][2] + bx, acc[mt][nt][3] + by);
            }
        }
    }
}

// ---------------- launch ------------------------------------------------------
extern "C" void kernel_launch(void* const* d_in, const int* in_sizes, int n_in,
                              void* d_out, int out_size)
{
    const int*   car    = (const int*)  d_in[0];
    const int*   reg    = (const int*)  d_in[1];
    const int*   poi    = (const int*)  d_in[2];
    const int*   week   = (const int*)  d_in[3];
    const int*   timei  = (const int*)  d_in[4];
    const float* car_e  = (const float*)d_in[5];
    const float* reg_e  = (const float*)d_in[6];
    const float* poi_e  = (const float*)d_in[7];
    const float* week_e = (const float*)d_in[8];
    const float* time_e = (const float*)d_in[9];
    const float* Wih0   = (const float*)d_in[10];
    const float* Whh0   = (const float*)d_in[11];
    const float* bih0   = (const float*)d_in[12];
    const float* bhh0   = (const float*)d_in[13];
    const float* Wih1   = (const float*)d_in[14];
    const float* Whh1   = (const float*)d_in[15];
    const float* bih1   = (const float*)d_in[16];
    const float* bhh1   = (const float*)d_in[17];
    const float* Wout   = (const float*)d_in[18];
    const float* bout   = (const float*)d_in[19];
    float* out = (float*)d_out;

    fp16 *x, *h1, *ha, *hb;
    float *c, *bias0, *bias1;
    fp16 *w0h, *w0l, *w1h, *w1l, *woh, *wol;
    cudaGetSymbolAddress((void**)&x,     g_x);
    cudaGetSymbolAddress((void**)&h1,    g_h1);
    cudaGetSymbolAddress((void**)&ha,    g_ha);
    cudaGetSymbolAddress((void**)&hb,    g_hb);
    cudaGetSymbolAddress((void**)&c,     g_c);
    cudaGetSymbolAddress((void**)&bias0, g_bias0);
    cudaGetSymbolAddress((void**)&bias1, g_bias1);
    cudaGetSymbolAddress((void**)&w0h, g_w0_hi); cudaGetSymbolAddress((void**)&w0l, g_w0_lo);
    cudaGetSymbolAddress((void**)&w1h, g_w1_hi); cudaGetSymbolAddress((void**)&w1l, g_w1_lo);
    cudaGetSymbolAddress((void**)&woh, g_wo_hi); cudaGetSymbolAddress((void**)&wol, g_wo_lo);

    cudaFuncSetAttribute(gemm_rec,  cudaFuncAttributeMaxDynamicSharedMemorySize, SM_BYTES);
    cudaFuncSetAttribute(gemm_head, cudaFuncAttributeMaxDynamicSharedMemorySize, SM_BYTES);

    fp16* hbuf[2] = { ha, hb };

    prep_bias<<<(G_SZ + 255) / 256, 256>>>(bih0, bhh0, bih1, bhh1);
    // layer0 image: kc 0..3 = Whh0 (K=256), kc 4 = Wih0 (K=39), 4 tiles, perm
    prep_wimg<<<(4L * 4 * 16384 + 255) / 256, 256>>>(Whh0, 256, 1024, 1, w0h, w0l, 5, 0, 4, 4);
    prep_wimg<<<(4L * 1 * 16384 + 255) / 256, 256>>>(Wih0,  39, 1024, 1, w0h, w0l, 5, 4, 1, 4);
    // layer1 image: kc 0..3 = Whh1, kc 4..7 = Wih1
    prep_wimg<<<(4L * 4 * 16384 + 255) / 256, 256>>>(Whh1, 256, 1024, 1, w1h, w1l, 8, 0, 4, 4);
    prep_wimg<<<(4L * 4 * 16384 + 255) / 256, 256>>>(Wih1, 256, 1024, 1, w1h, w1l, 8, 4, 4, 4);
    // head image: 2 tiles, no perm
    prep_wimg<<<(2L * 4 * 16384 + 255) / 256, 256>>>(Wout, 256, 500, 0, woh, wol, 4, 0, 4, 2);

    gather_kernel<<<((long)ROWS * XPAD + 255) / 256, 256>>>(
        car, reg, poi, week, timei, car_e, reg_e, poi_e, week_e, time_e);

    const dim3 grid(8, B_SZ / 128);

    // layer0: gates_t = [h_{t-1} | x_t] @ [Whh0|Wih0]^T + b0 ; t=0 x-only, c=0
    gemm_rec<<<grid, 256, SM_BYTES>>>(ha, x + 0 * XPAD, T_SZ * XPAD, 4, 4, 5,
                                      w0h, w0l, bias0, c, 1, hbuf[0], h1, 0);
    for (int t = 1; t < T_SZ; ++t)
        gemm_rec<<<grid, 256, SM_BYTES>>>(hbuf[(t - 1) & 1], x + t * XPAD, T_SZ * XPAD, 4, 0, 5,
                                          w0h, w0l, bias0, c, 0, hbuf[t & 1], h1, t);

    // layer1: gates_t = [h2_{t-1} | h1_t] @ [Whh1|Wih1]^T + b1 ; t=0 h1-only, c=0
    gemm_rec<<<grid, 256, SM_BYTES>>>(ha, h1 + 0 * H_SZ, T_SZ * H_SZ, 4, 4, 8,
                                      w1h, w1l, bias1, c, 1, hbuf[0], nullptr, 0);
    for (int t = 1; t < T_SZ; ++t)
        gemm_rec<<<grid, 256, SM_BYTES>>>(hbuf[(t - 1) & 1], h1 + t * H_SZ, T_SZ * H_SZ, 4, 0, 8,
                                          w1h, w1l, bias1, c, 0, hbuf[t & 1], nullptr, t);

    // output head: out = h_last @ Wout^T + bout (N padded 512, valid 500)
    gemm_head<<<dim3(4, B_SZ / 128), 256, SM_BYTES>>>(
        hbuf[1], woh, wol, bout, out, N_LABELS, N_LABELS);
}

// round 8
// speedup vs baseline: 1.4045x; 1.4045x over previous
#include <cuda_runtime.h>
#include <cuda_fp16.h>
#include <cstdint>
#include <math.h>

#define B_SZ     16384
#define T_SZ     10
#define H_SZ     256
#define G_SZ     1024
#define N_LABELS 500
#define ROWS     (B_SZ * T_SZ)     // 163840
#define XPAD     64
#define XGSTRIDE 10240             // T_SZ * G_SZ

typedef unsigned long long u64;
typedef unsigned int u32;
typedef __half fp16;

// ---------------- device scratch (no allocations allowed) --------------------
__device__ fp16  g_x   [(size_t)ROWS * XPAD];      // gathered input, fp16
__device__ fp16  g_xg  [(size_t)ROWS * G_SZ];      // input projections (fp16, gate-permuted, bias folded)
__device__ fp16  g_h1  [(size_t)ROWS * H_SZ];      // layer0 outputs, fp16
__device__ fp16  g_ha  [(size_t)B_SZ * H_SZ];      // h ping-pong buffers
__device__ fp16  g_hb  [(size_t)B_SZ * H_SZ];
__device__ float g_c   [(size_t)B_SZ * H_SZ];
__device__ float g_bias0[G_SZ];                    // permuted combined biases
__device__ float g_bias1[G_SZ];
// weight tile images (fp16, pre-swizzled): [tile*nkc+kc][256][64]
__device__ fp16 g_wih0[4 * 1 * 16384];
__device__ fp16 g_whh0[4 * 4 * 16384];
__device__ fp16 g_wih1[4 * 4 * 16384];
__device__ fp16 g_whh1[4 * 4 * 16384];
__device__ fp16 g_wout[2 * 4 * 16384];

// ---------------- PTX helpers ------------------------------------------------
__device__ __forceinline__ u32 smem_u32(const void* p) {
    u32 a; asm("{ .reg .u64 t; cvta.to.shared.u64 t, %1; cvt.u32.u64 %0, t; }"
               : "=r"(a) : "l"(p));
    return a;
}
__device__ __forceinline__ void cp16(u32 dst, const void* src) {
    asm volatile("cp.async.cg.shared.global [%0], [%1], 16;" :: "r"(dst), "l"(src));
}
__device__ __forceinline__ void cp_commit() { asm volatile("cp.async.commit_group;"); }
template <int N> __device__ __forceinline__ void cp_wait() {
    asm volatile("cp.async.wait_group %0;" :: "n"(N));
}
__device__ __forceinline__ void ldm4(u32& r0, u32& r1, u32& r2, u32& r3, u32 addr) {
    asm volatile("ldmatrix.sync.aligned.m8n8.x4.shared.b16 {%0,%1,%2,%3}, [%4];"
                 : "=r"(r0), "=r"(r1), "=r"(r2), "=r"(r3) : "r"(addr));
}
__device__ __forceinline__ void mma16(float* d, const u32* a, const u32* b) {
    asm volatile("mma.sync.aligned.m16n8k16.row.col.f32.f16.f16.f32 "
                 "{%0,%1,%2,%3}, {%4,%5,%6,%7}, {%8,%9}, {%0,%1,%2,%3};"
                 : "+f"(d[0]), "+f"(d[1]), "+f"(d[2]), "+f"(d[3])
                 : "r"(a[0]), "r"(a[1]), "r"(a[2]), "r"(a[3]), "r"(b[0]), "r"(b[1]));
}

// ---------------- prep kernels ----------------------------------------------
// permuted combined biases: out index p = 4j+g  <-  n = g*256+j
__global__ void prep_bias(const float* bih0, const float* bhh0,
                          const float* bih1, const float* bhh1) {
    int p = blockIdx.x * blockDim.x + threadIdx.x;
    if (p < G_SZ) {
        int j = p >> 2, g = p & 3, n = g * 256 + j;
        g_bias0[p] = bih0[n] + bhh0[n];
        g_bias1[p] = bih1[n] + bhh1[n];
    }
}

// pack W[Nrows,Kw] into fp16 swizzled tile image; perm: gate interleave rows
__global__ void prep_w(const float* __restrict__ W, int Kw, int Nrows,
                       int nkc, long total, int perm, fp16* __restrict__ img) {
    long id = (long)blockIdx.x * blockDim.x + threadIdx.x;
    if (id >= total) return;
    int c  = (int)(id & 63);
    int r  = (int)((id >> 6) & 255);
    long tc = id >> 14;
    int kc = (int)(tc % nkc), nt = (int)(tc / nkc);
    int p = nt * 256 + r;
    int n = perm ? ((p & 3) * 256 + (p >> 2)) : p;
    int k = kc * 64 + c;
    float v = (n < Nrows && k < Kw) ? W[(size_t)n * Kw + k] : 0.f;
    size_t pos = ((size_t)tc * 256 + r) * 64 + (size_t)((((c >> 3) ^ (r & 7)) << 3) | (c & 7));
    img[pos] = __float2half(v);
}

// embedding gather -> fp16 X [ROWS, 64]
__global__ void gather_kernel(const int* __restrict__ car, const int* __restrict__ reg,
                              const int* __restrict__ poi, const int* __restrict__ week,
                              const int* __restrict__ timei,
                              const float* __restrict__ ce, const float* __restrict__ re,
                              const float* __restrict__ pe, const float* __restrict__ we,
                              const float* __restrict__ te) {
    long i = (long)blockIdx.x * blockDim.x + threadIdx.x;
    if (i >= (long)ROWS * XPAD) return;
    long r = i / XPAD; int j = (int)(i % XPAD);
    float v = 0.f;
    if      (j < 16) v = ce[(size_t)car  [r] * 16 + j];
    else if (j < 24) v = re[(size_t)reg  [r] * 8  + (j - 16)];
    else if (j < 28) v = pe[(size_t)poi  [r] * 4  + (j - 24)];
    else if (j < 31) v = we[(size_t)week [r] * 3  + (j - 28)];
    else if (j < 39) v = te[(size_t)timei[r] * 8  + (j - 31)];
    g_x[i] = __float2half(v);
}

// ---------------- GEMM config ------------------------------------------------
// BM=128, BN=128, BK=64; 256 thr, 8 warps 2x4 (warp tile 64x32); single fp16 pass.
// Stage = A 16KB | W 16KB.
#define STG_BYTES 32768
#define SM_BYTES  (2 * STG_BYTES)   // 65536

#define GEMM_MAINLOOP(A_, lda_, W_, nkc_, m0_, tile_, rowbase_)                        \
    const int au = tid & 7, ar = tid >> 3;                                             \
    auto load_stage = [&](int s, int kc) {                                             \
        u32 base = sb + s * STG_BYTES;                                                 \
        const size_t acol = (size_t)kc * 64 + au * 8;                                  \
        _Pragma("unroll")                                                              \
        for (int i = 0; i < 4; i++) {                                                  \
            int r = ar + i * 32;                                                       \
            u32 d = base + ((r * 64 + ((au ^ (r & 7)) << 3)) << 1);                    \
            cp16(d, A_ + (size_t)(m0_ + r) * lda_ + acol);                             \
        }                                                                              \
        const size_t ib = (size_t)(tile_ * nkc_ + kc) * 16384 + (size_t)rowbase_ * 64; \
        _Pragma("unroll")                                                              \
        for (int i = 0; i < 4; i++) {                                                  \
            int j = tid + i * 256;                                                     \
            cp16(base + 16384 + j * 16, W_ + ib + (size_t)j * 8);                      \
        }                                                                              \
        cp_commit();                                                                   \
    };                                                                                 \
    const int lrow = lid & 15, lk = lid >> 4;                                          \
    load_stage(0, 0);                                                                  \
    for (int kc = 0; kc < nkc_; ++kc) {                                                \
        if (kc + 1 < nkc_) { load_stage((kc + 1) & 1, kc + 1); cp_wait<1>(); }         \
        else              { cp_wait<0>(); }                                            \
        __syncthreads();                                                               \
        const u32 aBase = sb + (kc & 1) * STG_BYTES;                                   \
        const u32 bBase = aBase + 16384;                                               \
        _Pragma("unroll")                                                              \
        for (int k16 = 0; k16 < 4; ++k16) {                                            \
            const int kb8 = k16 * 2 + lk;                                              \
            u32 bh[4][2];                                                              \
            _Pragma("unroll")                                                          \
            for (int blk = 0; blk < 2; ++blk) {                                        \
                int row = n_w + blk * 16 + lrow;                                       \
                u32 ad = bBase + ((row * 64 + ((kb8 ^ (row & 7)) << 3)) << 1);         \
                u32 r0, r1, r2, r3;                                                    \
                ldm4(r0, r1, r2, r3, ad);                                              \
                bh[blk * 2][0] = r0; bh[blk * 2][1] = r2;                              \
                bh[blk * 2 + 1][0] = r1; bh[blk * 2 + 1][1] = r3;                      \
            }                                                                          \
            _Pragma("unroll")                                                          \
            for (int mt = 0; mt < 4; ++mt) {                                           \
                int row = m_w + mt * 16 + lrow;                                        \
                u32 ad = aBase + ((row * 64 + ((kb8 ^ (row & 7)) << 3)) << 1);         \
                u32 af[4];                                                             \
                ldm4(af[0], af[1], af[2], af[3], ad);                                  \
                _Pragma("unroll")                                                      \
                for (int nt = 0; nt < 4; ++nt) mma16(acc[mt][nt], af, bh[nt]);         \
            }                                                                          \
        }                                                                              \
        __syncthreads();                                                               \
    }

// ---------------- generic GEMM (xg projections fp16-out, head fp32-out) -------
template <typename OutT>
__global__ void __launch_bounds__(256)
gemm_mma(const fp16* __restrict__ A, int lda,
         const fp16* __restrict__ W, int nkc,
         const float* __restrict__ bias,
         OutT* __restrict__ C, int ldc, int Nvalid)
{
    extern __shared__ __align__(1024) char sm[];
    const u32 sb = smem_u32(sm);
    const int tid = threadIdx.x, wid = tid >> 5, lid = tid & 31;
    const int m0 = blockIdx.y * 128;
    const int n0 = blockIdx.x * 128;
    const int tile = n0 >> 8, rowbase = n0 & 255;
    const int m_w = (wid >> 2) * 64, n_w = (wid & 2 ? 64 : 0) + (wid & 1) * 32;

    float acc[4][4][4];
#pragma unroll
    for (int a = 0; a < 4; a++)
#pragma unroll
        for (int b = 0; b < 4; b++)
#pragma unroll
            for (int e = 0; e < 4; e++) acc[a][b][e] = 0.f;

    GEMM_MAINLOOP(A, lda, W, nkc, m0, tile, rowbase)

#pragma unroll
    for (int mt = 0; mt < 4; ++mt) {
        int r0 = m0 + m_w + mt * 16 + (lid >> 2);
#pragma unroll
        for (int nt = 0; nt < 4; ++nt) {
            int cN = n0 + n_w + nt * 8 + (lid & 3) * 2;
            if (cN < Nvalid) {
                float bx = bias[cN], by = bias[cN + 1];
                float a0 = acc[mt][nt][0] + bx, a1 = acc[mt][nt][1] + by;
                float a2 = acc[mt][nt][2] + bx, a3 = acc[mt][nt][3] + by;
                if constexpr (sizeof(OutT) == 2) {
                    *(__half2*)((fp16*)C + (size_t)r0 * ldc + cN) =
                        __floats2half2_rn(a0, a1);
                    *(__half2*)((fp16*)C + (size_t)(r0 + 8) * ldc + cN) =
                        __floats2half2_rn(a2, a3);
                } else {
                    *(float2*)((float*)C + (size_t)r0 * ldc + cN) = make_float2(a0, a1);
                    *(float2*)((float*)C + (size_t)(r0 + 8) * ldc + cN) = make_float2(a2, a3);
                }
            }
        }
    }
}

// ---------------- recurrent GEMM with fused LSTM cell epilogue ----------------
// N=1024 (gate-permuted p=4j+g), M=B_SZ, K=256 (nkc=4); xg fp16 addend.
__global__ void __launch_bounds__(256)
gemm_rec(const fp16* __restrict__ A,
         const fp16* __restrict__ W,
         const fp16* __restrict__ xg, int t,
         float* __restrict__ c, fp16* __restrict__ hout, fp16* __restrict__ h1out)
{
    extern __shared__ __align__(1024) char sm[];
    const u32 sb = smem_u32(sm);
    const int tid = threadIdx.x, wid = tid >> 5, lid = tid & 31;
    const int m0 = blockIdx.y * 128;
    const int n0 = blockIdx.x * 128;
    const int tile = n0 >> 8, rowbase = n0 & 255;
    const int m_w = (wid >> 2) * 64, n_w = (wid & 2 ? 64 : 0) + (wid & 1) * 32;
    const int nkc = 4, lda = H_SZ;

    float acc[4][4][4];
#pragma unroll
    for (int a = 0; a < 4; a++)
#pragma unroll
        for (int b = 0; b < 4; b++)
#pragma unroll
            for (int e = 0; e < 4; e++) acc[a][b][e] = 0.f;

    GEMM_MAINLOOP(A, lda, W, nkc, m0, tile, rowbase)

    // fused cell epilogue: exchange half-quadruples between lane pairs
    const int odd = lid & 1;
#pragma unroll
    for (int mt = 0; mt < 4; ++mt) {
        int r0 = m0 + m_w + mt * 16 + (lid >> 2);
#pragma unroll
        for (int nt = 0; nt < 4; ++nt) {
            float* a4 = acc[mt][nt];
            int p = n0 + n_w + nt * 8 + (lid & 3) * 2;
            int j = p >> 2;
            float s0 = odd ? a4[0] : a4[2];
            float s1 = odd ? a4[1] : a4[3];
            float r0v = __shfl_xor_sync(0xFFFFFFFFu, s0, 1);
            float r1v = __shfl_xor_sync(0xFFFFFFFFu, s1, 1);
            float gi, gf, gg, go;
            int row;
            if (odd) { gi = r0v;  gf = r1v;  gg = a4[2]; go = a4[3]; row = r0 + 8; }
            else     { gi = a4[0]; gf = a4[1]; gg = r0v; go = r1v;  row = r0; }
            const fp16* xrow = xg + (size_t)row * XGSTRIDE + (size_t)t * G_SZ + 4 * j;
            __half2 x01 = *(const __half2*)(xrow);
            __half2 x23 = *(const __half2*)(xrow + 2);
            float2 f01 = __half22float2(x01);
            float2 f23 = __half22float2(x23);
            gi += f01.x; gf += f01.y; gg += f23.x; go += f23.y;
            gi = 1.f / (1.f + expf(-gi));
            gf = 1.f / (1.f + expf(-gf));
            go = 1.f / (1.f + expf(-go));
            gg = tanhf(gg);
            size_t ci = (size_t)row * H_SZ + j;
            float cn = gf * c[ci] + gi * gg;
            float hn = go * tanhf(cn);
            c[ci] = cn;
            hout[ci] = __float2half(hn);
            if (h1out) h1out[((size_t)row * T_SZ + t) * H_SZ + j] = __float2half(hn);
        }
    }
}

// ---------------- t=0 cell (no GEMM; gates = xg, c_old = 0) -------------------
__global__ void cell_t0(const fp16* __restrict__ xg,
                        float* __restrict__ c, fp16* __restrict__ hout,
                        fp16* __restrict__ h1out) {
    int idx = blockIdx.x * blockDim.x + threadIdx.x;
    if (idx >= B_SZ * H_SZ) return;
    int b = idx >> 8, j = idx & 255;
    const fp16* xrow = xg + (size_t)b * XGSTRIDE + 4 * j;
    __half2 x01 = *(const __half2*)(xrow);
    __half2 x23 = *(const __half2*)(xrow + 2);
    float2 f01 = __half22float2(x01);
    float2 f23 = __half22float2(x23);
    float gi = 1.f / (1.f + expf(-f01.x));
    float gf = 1.f / (1.f + expf(-f01.y));
    float gg = tanhf(f23.x);
    float go = 1.f / (1.f + expf(-f23.y));
    float cn = gi * gg;
    float hn = go * tanhf(cn);
    c[idx] = cn;
    hout[idx] = __float2half(hn);
    if (h1out) h1out[(size_t)b * T_SZ * H_SZ + j] = __float2half(hn);
}

// ---------------- launch ------------------------------------------------------
extern "C" void kernel_launch(void* const* d_in, const int* in_sizes, int n_in,
                              void* d_out, int out_size)
{
    const int*   car    = (const int*)  d_in[0];
    const int*   reg    = (const int*)  d_in[1];
    const int*   poi    = (const int*)  d_in[2];
    const int*   week   = (const int*)  d_in[3];
    const int*   timei  = (const int*)  d_in[4];
    const float* car_e  = (const float*)d_in[5];
    const float* reg_e  = (const float*)d_in[6];
    const float* poi_e  = (const float*)d_in[7];
    const float* week_e = (const float*)d_in[8];
    const float* time_e = (const float*)d_in[9];
    const float* Wih0   = (const float*)d_in[10];
    const float* Whh0   = (const float*)d_in[11];
    const float* bih0   = (const float*)d_in[12];
    const float* bhh0   = (const float*)d_in[13];
    const float* Wih1   = (const float*)d_in[14];
    const float* Whh1   = (const float*)d_in[15];
    const float* bih1   = (const float*)d_in[16];
    const float* bhh1   = (const float*)d_in[17];
    const float* Wout   = (const float*)d_in[18];
    const float* bout   = (const float*)d_in[19];
    float* out = (float*)d_out;

    fp16 *x, *xg, *h1, *ha, *hb;
    float *c, *bias0, *bias1;
    fp16 *wih0, *whh0, *wih1, *whh1, *wout;
    cudaGetSymbolAddress((void**)&x,     g_x);
    cudaGetSymbolAddress((void**)&xg,    g_xg);
    cudaGetSymbolAddress((void**)&h1,    g_h1);
    cudaGetSymbolAddress((void**)&ha,    g_ha);
    cudaGetSymbolAddress((void**)&hb,    g_hb);
    cudaGetSymbolAddress((void**)&c,     g_c);
    cudaGetSymbolAddress((void**)&bias0, g_bias0);
    cudaGetSymbolAddress((void**)&bias1, g_bias1);
    cudaGetSymbolAddress((void**)&wih0, g_wih0);
    cudaGetSymbolAddress((void**)&whh0, g_whh0);
    cudaGetSymbolAddress((void**)&wih1, g_wih1);
    cudaGetSymbolAddress((void**)&whh1, g_whh1);
    cudaGetSymbolAddress((void**)&wout, g_wout);

    cudaFuncSetAttribute(gemm_mma<fp16>,  cudaFuncAttributeMaxDynamicSharedMemorySize, SM_BYTES);
    cudaFuncSetAttribute(gemm_mma<float>, cudaFuncAttributeMaxDynamicSharedMemorySize, SM_BYTES);
    cudaFuncSetAttribute(gemm_rec,        cudaFuncAttributeMaxDynamicSharedMemorySize, SM_BYTES);

    fp16* hbuf[2] = { ha, hb };

    prep_bias<<<(G_SZ + 255) / 256, 256>>>(bih0, bhh0, bih1, bhh1);
    {
        long t0 = 4L * 1 * 16384;
        prep_w<<<(t0 + 255) / 256, 256>>>(Wih0, 39, 1024, 1, t0, 1, wih0);
        long t1 = 4L * 4 * 16384;
        prep_w<<<(t1 + 255) / 256, 256>>>(Whh0, 256, 1024, 4, t1, 1, whh0);
        prep_w<<<(t1 + 255) / 256, 256>>>(Wih1, 256, 1024, 4, t1, 1, wih1);
        prep_w<<<(t1 + 255) / 256, 256>>>(Whh1, 256, 1024, 4, t1, 1, whh1);
        long t2 = 2L * 4 * 16384;
        prep_w<<<(t2 + 255) / 256, 256>>>(Wout, 256, 500, 4, t2, 0, wout);
    }
    gather_kernel<<<((long)ROWS * XPAD + 255) / 256, 256>>>(
        car, reg, poi, week, timei, car_e, reg_e, poi_e, week_e, time_e);

    // layer0 input projection: xg = X @ Wih0p^T + bias0 (gate-permuted, fp16)
    gemm_mma<fp16><<<dim3(8, ROWS / 128), 256, SM_BYTES>>>(
        x, XPAD, wih0, 1, bias0, xg, G_SZ, G_SZ);

    // layer0 recurrence (cell fused into GEMM epilogue)
    cell_t0<<<(B_SZ * H_SZ) / 256, 256>>>(xg, c, hbuf[0], h1);
    for (int t = 1; t < T_SZ; ++t)
        gemm_rec<<<dim3(8, B_SZ / 128), 256, SM_BYTES>>>(
            hbuf[(t - 1) & 1], whh0, xg, t, c, hbuf[t & 1], h1);

    // layer1 input projection: xg = H1 @ Wih1^T + bias1 (gate-permuted, fp16)
    gemm_mma<fp16><<<dim3(8, ROWS / 128), 256, SM_BYTES>>>(
        h1, H_SZ, wih1, 4, bias1, xg, G_SZ, G_SZ);

    // layer1 recurrence
    cell_t0<<<(B_SZ * H_SZ) / 256, 256>>>(xg, c, hbuf[0], nullptr);
    for (int t = 1; t < T_SZ; ++t)
        gemm_rec<<<dim3(8, B_SZ / 128), 256, SM_BYTES>>>(
            hbuf[(t - 1) & 1], whh1, xg, t, c, hbuf[t & 1], nullptr);

    // output head: out = h_last @ Wout^T + bout (N padded 512, valid 500)
    gemm_mma<float><<<dim3(4, B_SZ / 128), 256, SM_BYTES>>>(
        hbuf[1], H_SZ, wout, 4, bout, out, N_LABELS, N_LABELS);
}